// round 1
// baseline (speedup 1.0000x reference)
#include <cuda_runtime.h>
#include <math.h>

#define BB 8
#define TT 8192
#define DV 1024
#define DQ 768
#define KREP 6
#define NH 8
#define HD 128
#define CC 18   // K_REP*3 candidates

// ---------------- scratch (no allocations allowed) ----------------
__device__ __align__(16) float g_h[2 * BB * DV];         // hidden after LN+ReLU
__device__ __align__(16) float g_mu[BB * DV];
__device__ __align__(16) float g_isg[BB * DV];           // 1/sigma
__device__ __align__(16) float g_rep[BB * KREP * DV];    // gathered features
__device__ __align__(16) float g_qkv[BB * KREP * 3 * DV];
__device__ float g_attn[BB * NH * KREP * KREP];
__device__ __align__(16) float g_ao[BB * KREP * DV];     // attention output

__device__ __forceinline__ float warp_sum(float v) {
#pragma unroll
    for (int o = 16; o; o >>= 1) v += __shfl_xor_sync(0xffffffffu, v, o);
    return v;
}

// ---------------- kernel 1: Linear(768->1024) + LayerNorm + ReLU ----------------
__global__ void k_hidden(const float* __restrict__ q,
                         const float* __restrict__ w1m, const float* __restrict__ b1m,
                         const float* __restrict__ gm,  const float* __restrict__ btm,
                         const float* __restrict__ w1s, const float* __restrict__ b1s,
                         const float* __restrict__ gs,  const float* __restrict__ bts) {
    int b = blockIdx.x, br = blockIdx.y;
    const float* w1 = br ? w1s : w1m;
    const float* b1 = br ? b1s : b1m;
    const float* g  = br ? gs  : gm;
    const float* bt = br ? bts : btm;

    __shared__ float xs[DQ];
    __shared__ float hs[DV];
    __shared__ float red[8], red2[8];
    __shared__ float mean_s, rstd_s;

    int tid = threadIdx.x, lane = tid & 31, wid = tid >> 5;
    for (int i = tid; i < DQ; i += 256) xs[i] = q[b * DQ + i];
    __syncthreads();

    for (int o = wid; o < DV; o += 8) {
        const float* wr = w1 + o * DQ;
        float acc = 0.f;
        for (int i = lane; i < DQ; i += 32) acc += wr[i] * xs[i];
        acc = warp_sum(acc);
        if (lane == 0) hs[o] = acc + b1[o];
    }
    __syncthreads();

    float s = 0.f;
    for (int i = tid; i < DV; i += 256) s += hs[i];
    s = warp_sum(s);
    if (lane == 0) red[wid] = s;
    __syncthreads();
    if (tid == 0) {
        float m = 0.f;
        for (int i = 0; i < 8; i++) m += red[i];
        mean_s = m / (float)DV;
    }
    __syncthreads();
    float m = mean_s;
    float v = 0.f;
    for (int i = tid; i < DV; i += 256) { float d = hs[i] - m; v += d * d; }
    v = warp_sum(v);
    if (lane == 0) red2[wid] = v;
    __syncthreads();
    if (tid == 0) {
        float vv = 0.f;
        for (int i = 0; i < 8; i++) vv += red2[i];
        rstd_s = rsqrtf(vv / (float)DV + 1e-5f);
    }
    __syncthreads();
    float rstd = rstd_s;
    float* dst = g_h + (br * BB + b) * DV;
    for (int i = tid; i < DV; i += 256) {
        float val = (hs[i] - m) * rstd * g[i] + bt[i];
        dst[i] = fmaxf(val, 0.f);
    }
}

// ---------------- kernel 2: Linear(1024->1024) + (identity | softplus+eps) ----------------
__global__ void k_out2(const float* __restrict__ w2m, const float* __restrict__ b2m,
                       const float* __restrict__ w2s, const float* __restrict__ b2s,
                       float* __restrict__ o_mu, float* __restrict__ o_sg) {
    int b = blockIdx.x, br = blockIdx.y;
    const float* w2 = br ? w2s : w2m;
    const float* b2 = br ? b2s : b2m;

    __shared__ float hs[DV];
    int tid = threadIdx.x, lane = tid & 31, wid = tid >> 5;
    const float* src = g_h + (br * BB + b) * DV;
    for (int i = tid; i < DV; i += 256) hs[i] = src[i];
    __syncthreads();

    for (int o = wid; o < DV; o += 8) {
        const float* wr = w2 + o * DV;
        float acc = 0.f;
        for (int i = lane; i < DV; i += 32) acc += wr[i] * hs[i];
        acc = warp_sum(acc);
        if (lane == 0) {
            float val = acc + b2[o];
            if (br == 0) {
                g_mu[b * DV + o] = val;
                o_mu[b * DV + o] = val;
            } else {
                // stable softplus: max(x,0) + log1p(exp(-|x|))
                float sp = fmaxf(val, 0.f) + log1pf(expf(-fabsf(val)));
                float sg = sp + 1e-6f;
                o_sg[b * DV + o] = sg;
                g_isg[b * DV + o] = 1.f / sg;
            }
        }
    }
}

// ---------------- kernel 3: Mahalanobis distance (the 256 MB stream) ----------------
__global__ void k_dist(const float* __restrict__ vf, float* __restrict__ o_dist) {
    __shared__ float4 mus[DV / 4];
    __shared__ float4 iss[DV / 4];
    int b = blockIdx.y;
    int tid = threadIdx.x, lane = tid & 31, wid = tid >> 5;
    mus[tid] = ((const float4*)(g_mu + b * DV))[tid];
    iss[tid] = ((const float4*)(g_isg + b * DV))[tid];
    __syncthreads();

#pragma unroll
    for (int r = 0; r < 4; r++) {
        int t = blockIdx.x * 32 + wid * 4 + r;
        const float4* vr = (const float4*)(vf + ((size_t)b * TT + t) * DV);
        float acc = 0.f;
#pragma unroll 4
        for (int i = lane; i < DV / 4; i += 32) {
            float4 v = vr[i], mm = mus[i], ss = iss[i];
            float dx = v.x - mm.x, dy = v.y - mm.y, dz = v.z - mm.z, dw = v.w - mm.w;
            acc += dx * dx * ss.x + dy * dy * ss.y + dz * dz * ss.z + dw * dw * ss.w;
        }
        acc = warp_sum(acc);
        if (lane == 0) o_dist[b * TT + t] = acc;
    }
}

// ---------------- kernel 4: median (radix-select) + top-18 + diversify + gather ----------------
__global__ void k_select(const float* __restrict__ dist, const float* __restrict__ vf,
                         float* __restrict__ o_idx) {
    __shared__ float fs[TT];
    __shared__ unsigned hist[256];
    __shared__ unsigned sh_prefix;
    __shared__ int sh_k;
    __shared__ float rv[32];
    __shared__ int ri[32];
    __shared__ int cand[CC];
    __shared__ int sels[KREP];

    int b = blockIdx.x;
    int tid = threadIdx.x, lane = tid & 31, wid = tid >> 5;
    const float* drow = dist + b * TT;

    for (int i = tid; i < TT; i += 1024) fs[i] = drow[i];
    if (tid == 0) { sh_prefix = 0u; sh_k = (TT - 1) / 2; }  // lower median index = 4095
    __syncthreads();

    // dist >= 0, so float bit pattern order == value order. 4x 8-bit radix select.
    for (int pass = 0; pass < 4; pass++) {
        int shift = 24 - 8 * pass;
        if (tid < 256) hist[tid] = 0u;
        __syncthreads();
        unsigned pfx = sh_prefix;
        for (int i = tid; i < TT; i += 1024) {
            unsigned u = __float_as_uint(fs[i]);
            bool ok = (pass == 0) || ((u >> (shift + 8)) == pfx);
            if (ok) atomicAdd(&hist[(u >> shift) & 255u], 1u);
        }
        __syncthreads();
        if (tid == 0) {
            int k = sh_k;
            unsigned cum = 0;
            int bin = 0;
            for (; bin < 256; bin++) {
                unsigned h = hist[bin];
                if (cum + h > (unsigned)k) break;
                cum += h;
            }
            sh_prefix = (sh_prefix << 8) | (unsigned)bin;
            sh_k = k - (int)cum;
        }
        __syncthreads();
    }
    float med = __uint_as_float(sh_prefix);
    __syncthreads();

    // d2t = |dist - med| in place
    for (int i = tid; i < TT; i += 1024) fs[i] = fabsf(fs[i] - med);
    __syncthreads();

    const float FINF = __int_as_float(0x7f800000);
    // 18 iterative argmins with (value, index) lexicographic tie-break == lax.top_k order
    for (int c = 0; c < CC; c++) {
        float bv = FINF;
        int bi = 0x7fffffff;
        for (int i = tid; i < TT; i += 1024) {
            float v = fs[i];
            if (v < bv || (v == bv && i < bi)) { bv = v; bi = i; }
        }
#pragma unroll
        for (int o = 16; o; o >>= 1) {
            float ov = __shfl_xor_sync(0xffffffffu, bv, o);
            int oi = __shfl_xor_sync(0xffffffffu, bi, o);
            if (ov < bv || (ov == bv && oi < bi)) { bv = ov; bi = oi; }
        }
        if (lane == 0) { rv[wid] = bv; ri[wid] = bi; }
        __syncthreads();
        if (wid == 0) {
            bv = rv[lane]; bi = ri[lane];
#pragma unroll
            for (int o = 16; o; o >>= 1) {
                float ov = __shfl_xor_sync(0xffffffffu, bv, o);
                int oi = __shfl_xor_sync(0xffffffffu, bi, o);
                if (ov < bv || (ov == bv && oi < bi)) { bv = ov; bi = oi; }
            }
            if (lane == 0) { cand[c] = bi; fs[bi] = FINF; }
        }
        __syncthreads();
    }

    // greedy farthest-point diversify (serial; matches jnp.argmax first-occurrence)
    if (tid == 0) {
        const float NINF = __int_as_float(0xff800000);
        float candf[CC], mind[CC];
        int sel[KREP];
        for (int c = 0; c < CC; c++) candf[c] = (float)cand[c];
        for (int c = 0; c < CC; c++) mind[c] = fabsf(candf[c] - candf[0]);
        mind[0] = NINF;
        sel[0] = cand[0];
        for (int s = 1; s < KREP; s++) {
            int best = 0;
            float bm = NINF;
            for (int c = 0; c < CC; c++)
                if (mind[c] > bm) { bm = mind[c]; best = c; }
            sel[s] = cand[best];
            float cb = candf[best];
            for (int c = 0; c < CC; c++) mind[c] = fminf(mind[c], fabsf(candf[c] - cb));
            mind[best] = NINF;
        }
        for (int s = 0; s < KREP; s++) {
            sels[s] = sel[s];
            o_idx[b * KREP + s] = (float)sel[s];
        }
    }
    __syncthreads();

    // gather rep
    for (int kk = 0; kk < KREP; kk++) {
        int t = sels[kk];
        const float* src = vf + ((size_t)b * TT + t) * DV;
        float* dst = g_rep + (b * KREP + kk) * DV;
        if (tid < DV) dst[tid] = src[tid];
    }
}

// ---------------- kernel 5: QKV projection (48 rows x 3072 outputs) ----------------
__global__ void k_qkv(const float* __restrict__ w, const float* __restrict__ bias) {
    int tid = threadIdx.x, lane = tid & 31, wid = tid >> 5;
    int o = blockIdx.x * 8 + wid;  // [0, 3072)
    float wf[32];
    const float* wr = w + o * DV;
#pragma unroll
    for (int j = 0; j < 32; j++) wf[j] = wr[lane + 32 * j];
    float bs = bias[o];
    for (int r = 0; r < BB * KREP; r++) {
        const float* xr = g_rep + r * DV;
        float acc = 0.f;
#pragma unroll
        for (int j = 0; j < 32; j++) acc += wf[j] * xr[lane + 32 * j];
        acc = warp_sum(acc);
        if (lane == 0) g_qkv[r * 3 * DV + o] = acc + bs;
    }
}

// ---------------- kernel 6: 6-token attention per (b, h) ----------------
__global__ void k_attn() {
    int b = blockIdx.x, h = blockIdx.y;
    __shared__ float qs[KREP * HD], ks[KREP * HD], vs[KREP * HD];
    int tid = threadIdx.x, lane = tid & 31, wid = tid >> 5;

    for (int i = tid; i < KREP * HD; i += 192) {
        int row = i / HD, d = i % HD;
        const float* base = g_qkv + (b * KREP + row) * 3 * DV + h * HD + d;
        qs[i] = base[0];
        ks[i] = base[DV];
        vs[i] = base[2 * DV];
    }
    __syncthreads();

    int i = wid;  // 6 warps, one query row each
    float sc[KREP];
    const float scale = 0.08838834764831845f;  // 1/sqrt(128)
    for (int j = 0; j < KREP; j++) {
        float acc = 0.f;
#pragma unroll
        for (int m = 0; m < 4; m++) acc += qs[i * HD + lane + 32 * m] * ks[j * HD + lane + 32 * m];
        acc = warp_sum(acc);
        sc[j] = acc * scale;
    }
    float mx = sc[0];
    for (int j = 1; j < KREP; j++) mx = fmaxf(mx, sc[j]);
    float den = 0.f;
    for (int j = 0; j < KREP; j++) { sc[j] = expf(sc[j] - mx); den += sc[j]; }
    float rden = 1.f / den;
    for (int j = 0; j < KREP; j++) sc[j] *= rden;
    if (lane < KREP) g_attn[((b * NH + h) * KREP + i) * KREP + lane] = sc[lane];
    for (int d = lane; d < HD; d += 32) {
        float o = 0.f;
        for (int j = 0; j < KREP; j++) o += sc[j] * vs[j * HD + d];
        g_ao[(b * KREP + i) * DV + h * HD + d] = o;
    }
}

// ---------------- kernel 7: attention weight mean over heads ----------------
__global__ void k_attnmean(float* __restrict__ o_attn) {
    int b = blockIdx.x;
    int tid = threadIdx.x;
    if (tid < KREP * KREP) {
        float s = 0.f;
        for (int h = 0; h < NH; h++) s += g_attn[(b * NH + h) * KREP * KREP + tid];
        o_attn[b * KREP * KREP + tid] = s * (1.f / (float)NH);
    }
}

// ---------------- kernel 8: output projection ----------------
__global__ void k_oproj(const float* __restrict__ w, const float* __restrict__ bias,
                        float* __restrict__ o_ref) {
    int tid = threadIdx.x, lane = tid & 31, wid = tid >> 5;
    int o = blockIdx.x * 8 + wid;  // [0, 1024)
    float wf[32];
    const float* wr = w + o * DV;
#pragma unroll
    for (int j = 0; j < 32; j++) wf[j] = wr[lane + 32 * j];
    float bs = bias[o];
    for (int r = 0; r < BB * KREP; r++) {
        const float* xr = g_ao + r * DV;
        float acc = 0.f;
#pragma unroll
        for (int j = 0; j < 32; j++) acc += wf[j] * xr[lane + 32 * j];
        acc = warp_sum(acc);
        if (lane == 0) o_ref[r * DV + o] = acc + bs;
    }
}

// ---------------- launcher ----------------
extern "C" void kernel_launch(void* const* d_in, const int* in_sizes, int n_in,
                              void* d_out, int out_size) {
    const float* vf    = (const float*)d_in[0];
    const float* qe    = (const float*)d_in[1];
    const float* mu_w1 = (const float*)d_in[2];
    const float* mu_b1 = (const float*)d_in[3];
    const float* mu_g  = (const float*)d_in[4];
    const float* mu_bt = (const float*)d_in[5];
    const float* mu_w2 = (const float*)d_in[6];
    const float* mu_b2 = (const float*)d_in[7];
    const float* sg_w1 = (const float*)d_in[8];
    const float* sg_b1 = (const float*)d_in[9];
    const float* sg_g  = (const float*)d_in[10];
    const float* sg_bt = (const float*)d_in[11];
    const float* sg_w2 = (const float*)d_in[12];
    const float* sg_b2 = (const float*)d_in[13];
    const float* in_w  = (const float*)d_in[14];
    const float* in_b  = (const float*)d_in[15];
    const float* out_w = (const float*)d_in[16];
    const float* out_b = (const float*)d_in[17];

    float* out = (float*)d_out;
    // flattened f32 concat in reference return order
    float* o_ref  = out;                    // [8,6,1024]  49152
    float* o_idx  = out + 49152;            // [8,6]       48 (as float)
    float* o_dist = out + 49200;            // [8,8192]    65536
    float* o_mu   = out + 114736;           // [8,1024]    8192
    float* o_sg   = out + 122928;           // [8,1024]    8192
    float* o_attn = out + 131120;           // [8,6,6]     288

    k_hidden<<<dim3(BB, 2), 256>>>(qe, mu_w1, mu_b1, mu_g, mu_bt, sg_w1, sg_b1, sg_g, sg_bt);
    k_out2<<<dim3(BB, 2), 256>>>(mu_w2, mu_b2, sg_w2, sg_b2, o_mu, o_sg);
    k_dist<<<dim3(TT / 32, BB), 256>>>(vf, o_dist);
    k_select<<<BB, 1024>>>(o_dist, vf, o_idx);
    k_qkv<<<3 * DV / 8, 256>>>(in_w, in_b);
    k_attn<<<dim3(BB, NH), 192>>>();
    k_attnmean<<<BB, 64>>>(o_attn);
    k_oproj<<<DV / 8, 256>>>(out_w, out_b, o_ref);
}

// round 3
// speedup vs baseline: 3.9918x; 3.9918x over previous
#include <cuda_runtime.h>
#include <math.h>

#define BB 8
#define TT 8192
#define DV 1024
#define DQ 768
#define KREP 6
#define NH 8
#define HD 128
#define CC 18   // K_REP*3 candidates

// ---------------- scratch (no allocations allowed) ----------------
__device__ __align__(16) float g_pre[2 * BB * DV];       // pre-LN hidden
__device__ __align__(16) float g_h[2 * BB * DV];         // hidden after LN+ReLU
__device__ __align__(16) float g_mu[BB * DV];
__device__ __align__(16) float g_isg[BB * DV];           // 1/sigma
__device__ __align__(16) float g_rep[BB * KREP * DV];    // gathered features
__device__ __align__(16) float g_qkv[BB * KREP * 3 * DV];
__device__ __align__(16) float g_ao[BB * KREP * DV];     // attention output

__device__ __forceinline__ float warp_sum(float v) {
#pragma unroll
    for (int o = 16; o; o >>= 1) v += __shfl_xor_sync(0xffffffffu, v, o);
    return v;
}

// ---------------- kernel 1: Linear(768->1024), wide grid ----------------
__global__ void k_lin1(const float* __restrict__ q,
                       const float* __restrict__ w1m, const float* __restrict__ b1m,
                       const float* __restrict__ w1s, const float* __restrict__ b1s) {
    int b = blockIdx.y, br = blockIdx.z;
    const float* w1 = br ? w1s : w1m;
    const float* b1 = br ? b1s : b1m;
    __shared__ float xs[DQ];
    int tid = threadIdx.x, lane = tid & 31, wid = tid >> 5;
    for (int i = tid; i < DQ; i += 256) xs[i] = q[b * DQ + i];
    __syncthreads();
    int base = blockIdx.x * 64 + wid * 8;
#pragma unroll
    for (int oo = 0; oo < 8; oo++) {
        int o = base + oo;
        const float* wr = w1 + o * DQ;
        float acc = 0.f;
#pragma unroll
        for (int i = lane; i < DQ; i += 32) acc += wr[i] * xs[i];
        acc = warp_sum(acc);
        if (lane == 0) g_pre[(br * BB + b) * DV + o] = acc + b1[o];
    }
}

// ---------------- kernel 2: LayerNorm + ReLU ----------------
__global__ void k_ln(const float* __restrict__ gm, const float* __restrict__ btm,
                     const float* __restrict__ gs, const float* __restrict__ bts) {
    int b = blockIdx.x, br = blockIdx.y;
    const float* g  = br ? gs  : gm;
    const float* bt = br ? bts : btm;
    __shared__ float hs[DV];
    __shared__ float red[8], red2[8];
    __shared__ float mean_s, rstd_s;
    int tid = threadIdx.x, lane = tid & 31, wid = tid >> 5;
    const float* src = g_pre + (br * BB + b) * DV;
    for (int i = tid; i < DV; i += 256) hs[i] = src[i];
    __syncthreads();
    float s = 0.f;
    for (int i = tid; i < DV; i += 256) s += hs[i];
    s = warp_sum(s);
    if (lane == 0) red[wid] = s;
    __syncthreads();
    if (tid == 0) {
        float m = 0.f;
        for (int i = 0; i < 8; i++) m += red[i];
        mean_s = m / (float)DV;
    }
    __syncthreads();
    float m = mean_s;
    float v = 0.f;
    for (int i = tid; i < DV; i += 256) { float d = hs[i] - m; v += d * d; }
    v = warp_sum(v);
    if (lane == 0) red2[wid] = v;
    __syncthreads();
    if (tid == 0) {
        float vv = 0.f;
        for (int i = 0; i < 8; i++) vv += red2[i];
        rstd_s = rsqrtf(vv / (float)DV + 1e-5f);
    }
    __syncthreads();
    float rstd = rstd_s;
    float* dst = g_h + (br * BB + b) * DV;
    for (int i = tid; i < DV; i += 256) {
        float val = (hs[i] - m) * rstd * g[i] + bt[i];
        dst[i] = fmaxf(val, 0.f);
    }
}

// ---------------- kernel 3: Linear(1024->1024) + (mu | softplus) epilogue ----------------
__global__ void k_lin2(const float* __restrict__ w2m, const float* __restrict__ b2m,
                       const float* __restrict__ w2s, const float* __restrict__ b2s,
                       float* __restrict__ o_mu, float* __restrict__ o_sg) {
    int b = blockIdx.y, br = blockIdx.z;
    const float* w2 = br ? w2s : w2m;
    const float* b2 = br ? b2s : b2m;
    __shared__ float hs[DV];
    int tid = threadIdx.x, lane = tid & 31, wid = tid >> 5;
    const float* src = g_h + (br * BB + b) * DV;
    for (int i = tid; i < DV; i += 256) hs[i] = src[i];
    __syncthreads();
    int base = blockIdx.x * 64 + wid * 8;
#pragma unroll
    for (int oo = 0; oo < 8; oo++) {
        int o = base + oo;
        const float* wr = w2 + o * DV;
        float acc = 0.f;
#pragma unroll
        for (int i = lane; i < DV; i += 32) acc += wr[i] * hs[i];
        acc = warp_sum(acc);
        if (lane == 0) {
            float val = acc + b2[o];
            if (br == 0) {
                g_mu[b * DV + o] = val;
                o_mu[b * DV + o] = val;
            } else {
                float sp = fmaxf(val, 0.f) + log1pf(expf(-fabsf(val)));
                float sg = sp + 1e-6f;
                o_sg[b * DV + o] = sg;
                g_isg[b * DV + o] = 1.f / sg;
            }
        }
    }
}

// ---------------- kernel 4: Mahalanobis distance (the 256 MB stream) ----------------
__global__ void k_dist(const float* __restrict__ vf, float* __restrict__ o_dist) {
    __shared__ float4 mus[DV / 4];
    __shared__ float4 iss[DV / 4];
    int b = blockIdx.y;
    int tid = threadIdx.x, lane = tid & 31, wid = tid >> 5;
    if (tid < 256) mus[tid] = ((const float4*)(g_mu + b * DV))[tid];
    else           iss[tid - 256] = ((const float4*)(g_isg + b * DV))[tid - 256];
    __syncthreads();

    int t = blockIdx.x * 16 + wid;
    const float4* vr = (const float4*)(vf + ((size_t)b * TT + t) * DV);
    float acc = 0.f;
#pragma unroll
    for (int it = 0; it < 8; it++) {
        int i = lane + it * 32;
        float4 v = vr[i], mm = mus[i], ss = iss[i];
        float dx = v.x - mm.x, dy = v.y - mm.y, dz = v.z - mm.z, dw = v.w - mm.w;
        acc += dx * dx * ss.x + dy * dy * ss.y + dz * dz * ss.z + dw * dw * ss.w;
    }
    acc = warp_sum(acc);
    if (lane == 0) o_dist[b * TT + t] = acc;
}

// ---------------- kernel 5: median + top-18 (radix) + diversify + gather ----------------
__global__ void k_select(const float* __restrict__ dist, const float* __restrict__ vf,
                         float* __restrict__ o_idx, float* __restrict__ o_attn) {
    __shared__ float fs[TT];
    __shared__ unsigned hist[256];
    __shared__ unsigned long long sh_prefix;
    __shared__ int sh_k;
    __shared__ unsigned long long ckeys[CC];
    __shared__ int sh_cnt;
    __shared__ int sels[KREP];

    int b = blockIdx.x;
    int tid = threadIdx.x;
    const float* drow = dist + b * TT;

    for (int i = tid; i < TT; i += 1024) fs[i] = drow[i];
    if (tid == 0) { sh_prefix = 0ull; sh_k = (TT - 1) / 2; }  // lower median index
    __syncthreads();

    // median: dist >= 0 so float bits order == value order; 4x 8-bit radix select
    for (int pass = 0; pass < 4; pass++) {
        int shift = 24 - 8 * pass;
        if (tid < 256) hist[tid] = 0u;
        __syncthreads();
        unsigned pfx = (unsigned)sh_prefix;
        for (int i = tid; i < TT; i += 1024) {
            unsigned u = __float_as_uint(fs[i]);
            bool ok = (pass == 0) || ((u >> (shift + 8)) == pfx);
            if (ok) atomicAdd(&hist[(u >> shift) & 255u], 1u);
        }
        __syncthreads();
        if (tid == 0) {
            int k = sh_k;
            unsigned cum = 0;
            int bin = 0;
            for (; bin < 256; bin++) {
                unsigned h = hist[bin];
                if (cum + h > (unsigned)k) break;
                cum += h;
            }
            sh_prefix = (sh_prefix << 8) | (unsigned long long)bin;
            sh_k = k - (int)cum;
        }
        __syncthreads();
    }
    float med = __uint_as_float((unsigned)sh_prefix);
    __syncthreads();

    // d2t = |dist - med| in place
    for (int i = tid; i < TT; i += 1024) fs[i] = fabsf(fs[i] - med);
    if (tid == 0) { sh_prefix = 0ull; sh_k = CC - 1; sh_cnt = 0; }
    __syncthreads();

    // top-18 smallest by (value, idx): key = bits(d2t) << 13 | idx (45 bits, unique)
    // 6x 8-bit radix select for the 18th smallest key
    for (int pass = 0; pass < 6; pass++) {
        int shift = 40 - 8 * pass;
        if (tid < 256) hist[tid] = 0u;
        __syncthreads();
        unsigned long long pfx = sh_prefix;
        for (int i = tid; i < TT; i += 1024) {
            unsigned long long key =
                ((unsigned long long)__float_as_uint(fs[i]) << 13) | (unsigned)i;
            bool ok = (pass == 0) || ((key >> (shift + 8)) == pfx);
            if (ok) atomicAdd(&hist[(unsigned)(key >> shift) & 255u], 1u);
        }
        __syncthreads();
        if (tid == 0) {
            int k = sh_k;
            unsigned cum = 0;
            int bin = 0;
            for (; bin < 256; bin++) {
                unsigned h = hist[bin];
                if (cum + h > (unsigned)k) break;
                cum += h;
            }
            sh_prefix = (sh_prefix << 8) | (unsigned long long)bin;
            sh_k = k - (int)cum;
        }
        __syncthreads();
    }
    unsigned long long kt = sh_prefix;  // 18th-smallest key

    // collect: keys are unique so exactly CC keys <= kt
    for (int i = tid; i < TT; i += 1024) {
        unsigned long long key =
            ((unsigned long long)__float_as_uint(fs[i]) << 13) | (unsigned)i;
        if (key <= kt) {
            int p = atomicAdd(&sh_cnt, 1);
            if (p < CC) ckeys[p] = key;
        }
    }
    __syncthreads();

    if (tid == 0) {
        // insertion sort ascending key == lax.top_k order (value asc, idx asc on ties)
        for (int i = 1; i < CC; i++) {
            unsigned long long kv = ckeys[i];
            int j = i - 1;
            while (j >= 0 && ckeys[j] > kv) { ckeys[j + 1] = ckeys[j]; j--; }
            ckeys[j + 1] = kv;
        }
        int cand[CC];
        for (int c = 0; c < CC; c++) cand[c] = (int)(ckeys[c] & 0x1FFFull);

        // greedy farthest-point diversify (first-occurrence argmax)
        const float NINF = __int_as_float(0xff800000);
        float candf[CC], mind[CC];
        int sel[KREP];
        for (int c = 0; c < CC; c++) candf[c] = (float)cand[c];
        for (int c = 0; c < CC; c++) mind[c] = fabsf(candf[c] - candf[0]);
        mind[0] = NINF;
        sel[0] = cand[0];
        for (int s = 1; s < KREP; s++) {
            int best = 0;
            float bm = NINF;
            for (int c = 0; c < CC; c++)
                if (mind[c] > bm) { bm = mind[c]; best = c; }
            sel[s] = cand[best];
            float cb = candf[best];
            for (int c = 0; c < CC; c++) mind[c] = fminf(mind[c], fabsf(candf[c] - cb));
            mind[best] = NINF;
        }
        for (int s = 0; s < KREP; s++) {
            sels[s] = sel[s];
            o_idx[b * KREP + s] = (float)sel[s];
        }
    }
    __syncthreads();

    // zero attention-weight output for later atomicAdd accumulation
    if (tid < KREP * KREP) o_attn[b * KREP * KREP + tid] = 0.f;

    // gather rep
    for (int kk = 0; kk < KREP; kk++) {
        int t = sels[kk];
        const float* src = vf + ((size_t)b * TT + t) * DV;
        float* dst = g_rep + (b * KREP + kk) * DV;
        if (tid < DV) dst[tid] = src[tid];
    }
}

// ---------------- kernel 6: 48-row GEMM with smem-staged x ----------------
// mode 0: x=g_rep, out=g_qkv (stride 3*DV). mode 1: x=g_ao, out=out_ext (stride DV).
// grid.x = n_out/8, 256 threads
__global__ void k_gemm48(const float* __restrict__ w, const float* __restrict__ bias,
                         float* __restrict__ out_ext, int mode) {
    const float* x = mode ? g_ao : g_rep;
    float* out     = mode ? out_ext : g_qkv;
    int ostride    = mode ? DV : 3 * DV;

    __shared__ float4 xs[48 * 32];  // 48 rows x 128 floats = 24KB
    int tid = threadIdx.x, lane = tid & 31, wid = tid >> 5;
    int o = blockIdx.x * 8 + wid;
    const float4* wr = (const float4*)(w + o * DV);
    float acc[48];
#pragma unroll
    for (int r = 0; r < 48; r++) acc[r] = 0.f;

    for (int kc = 0; kc < 8; kc++) {
        __syncthreads();
        for (int i = tid; i < 48 * 32; i += 256)
            xs[i] = ((const float4*)(x + (i >> 5) * DV + kc * 128))[i & 31];
        __syncthreads();
        float4 wv = wr[kc * 32 + lane];
#pragma unroll
        for (int r = 0; r < 48; r++) {
            float4 xv = xs[r * 32 + lane];
            acc[r] += wv.x * xv.x + wv.y * xv.y + wv.z * xv.z + wv.w * xv.w;
        }
    }
#pragma unroll
    for (int off = 16; off; off >>= 1)
#pragma unroll
        for (int r = 0; r < 48; r++)
            acc[r] += __shfl_xor_sync(0xffffffffu, acc[r], off);
    float bs = bias[o];
#pragma unroll
    for (int r = 0; r < 48; r++)
        if (lane == (r & 31)) out[r * ostride + o] = acc[r] + bs;
}

// ---------------- kernel 7: 6-token attention per (b, h), fused head-mean ----------------
__global__ void k_attn(float* __restrict__ o_attn) {
    int b = blockIdx.x, h = blockIdx.y;
    __shared__ float qs[KREP * HD], ks[KREP * HD], vs[KREP * HD];
    int tid = threadIdx.x, lane = tid & 31, wid = tid >> 5;

    for (int i = tid; i < KREP * HD; i += 192) {
        int row = i / HD, d = i % HD;
        const float* base = g_qkv + (b * KREP + row) * 3 * DV + h * HD + d;
        qs[i] = base[0];
        ks[i] = base[DV];
        vs[i] = base[2 * DV];
    }
    __syncthreads();

    int i = wid;  // 6 warps, one query row each
    float sc[KREP];
    const float scale = 0.08838834764831845f;  // 1/sqrt(128)
    for (int j = 0; j < KREP; j++) {
        float acc = 0.f;
#pragma unroll
        for (int m = 0; m < 4; m++)
            acc += qs[i * HD + lane + 32 * m] * ks[j * HD + lane + 32 * m];
        acc = warp_sum(acc);
        sc[j] = acc * scale;
    }
    float mx = sc[0];
    for (int j = 1; j < KREP; j++) mx = fmaxf(mx, sc[j]);
    float den = 0.f;
    for (int j = 0; j < KREP; j++) { sc[j] = expf(sc[j] - mx); den += sc[j]; }
    float rden = 1.f / den;
    for (int j = 0; j < KREP; j++) sc[j] *= rden;
    if (lane < KREP)
        atomicAdd(&o_attn[(b * KREP + i) * KREP + lane], sc[lane] * (1.f / (float)NH));
    for (int d = lane; d < HD; d += 32) {
        float o = 0.f;
        for (int j = 0; j < KREP; j++) o += sc[j] * vs[j * HD + d];
        g_ao[(b * KREP + i) * DV + h * HD + d] = o;
    }
}

// ---------------- launcher ----------------
extern "C" void kernel_launch(void* const* d_in, const int* in_sizes, int n_in,
                              void* d_out, int out_size) {
    const float* vf    = (const float*)d_in[0];
    const float* qe    = (const float*)d_in[1];
    const float* mu_w1 = (const float*)d_in[2];
    const float* mu_b1 = (const float*)d_in[3];
    const float* mu_g  = (const float*)d_in[4];
    const float* mu_bt = (const float*)d_in[5];
    const float* mu_w2 = (const float*)d_in[6];
    const float* mu_b2 = (const float*)d_in[7];
    const float* sg_w1 = (const float*)d_in[8];
    const float* sg_b1 = (const float*)d_in[9];
    const float* sg_g  = (const float*)d_in[10];
    const float* sg_bt = (const float*)d_in[11];
    const float* sg_w2 = (const float*)d_in[12];
    const float* sg_b2 = (const float*)d_in[13];
    const float* in_w  = (const float*)d_in[14];
    const float* in_b  = (const float*)d_in[15];
    const float* out_w = (const float*)d_in[16];
    const float* out_b = (const float*)d_in[17];

    float* out = (float*)d_out;
    float* o_ref  = out;                    // [8,6,1024]  49152
    float* o_idx  = out + 49152;            // [8,6]       48
    float* o_dist = out + 49200;            // [8,8192]    65536
    float* o_mu   = out + 114736;           // [8,1024]    8192
    float* o_sg   = out + 122928;           // [8,1024]    8192
    float* o_attn = out + 131120;           // [8,6,6]     288

    k_lin1<<<dim3(DV / 64, BB, 2), 256>>>(qe, mu_w1, mu_b1, sg_w1, sg_b1);
    k_ln<<<dim3(BB, 2), 256>>>(mu_g, mu_bt, sg_g, sg_bt);
    k_lin2<<<dim3(DV / 64, BB, 2), 256>>>(mu_w2, mu_b2, sg_w2, sg_b2, o_mu, o_sg);
    k_dist<<<dim3(TT / 16, BB), 512>>>(vf, o_dist);
    k_select<<<BB, 1024>>>(o_dist, vf, o_idx, o_attn);
    k_gemm48<<<3 * DV / 8, 256>>>(in_w, in_b, nullptr, 0);
    k_attn<<<dim3(BB, NH), 192>>>(o_attn);
    k_gemm48<<<DV / 8, 256>>>(out_w, out_b, o_ref, 1);
}

// round 4
// speedup vs baseline: 4.3773x; 1.0966x over previous
#include <cuda_runtime.h>
#include <math.h>

#define BB 8
#define TT 8192
#define DV 1024
#define DQ 768
#define KREP 6
#define NH 8
#define HD 128
#define CC 18     // K_REP*3 candidates
#define NB 4096   // radix histogram bins (12-bit)

// ---------------- scratch (no allocations allowed) ----------------
__device__ __align__(16) float g_pre[2 * BB * DV];       // pre-LN hidden
__device__ __align__(16) float g_mu[BB * DV];
__device__ __align__(16) float g_isg[BB * DV];           // 1/sigma
__device__ __align__(16) float g_rep[BB * KREP * DV];    // gathered features
__device__ __align__(16) float g_qkv[BB * KREP * 3 * DV];
__device__ __align__(16) float g_ao[BB * KREP * DV];     // attention output

__device__ __forceinline__ float warp_sum(float v) {
#pragma unroll
    for (int o = 16; o; o >>= 1) v += __shfl_xor_sync(0xffffffffu, v, o);
    return v;
}

// ---------------- kernel 1: Linear(768->1024), wide grid ----------------
__global__ void k_lin1(const float* __restrict__ q,
                       const float* __restrict__ w1m, const float* __restrict__ b1m,
                       const float* __restrict__ w1s, const float* __restrict__ b1s) {
    int b = blockIdx.y, br = blockIdx.z;
    const float* w1 = br ? w1s : w1m;
    const float* b1 = br ? b1s : b1m;
    __shared__ float xs[DQ];
    int tid = threadIdx.x, lane = tid & 31, wid = tid >> 5;
    for (int i = tid; i < DQ; i += 256) xs[i] = q[b * DQ + i];
    __syncthreads();
    int base = blockIdx.x * 64 + wid * 8;
#pragma unroll
    for (int oo = 0; oo < 8; oo++) {
        int o = base + oo;
        const float* wr = w1 + o * DQ;
        float acc = 0.f;
#pragma unroll
        for (int i = lane; i < DQ; i += 32) acc += wr[i] * xs[i];
        acc = warp_sum(acc);
        if (lane == 0) g_pre[(br * BB + b) * DV + o] = acc + b1[o];
    }
}

// ---------------- kernel 2: LN+ReLU (recomputed per block) + Linear(1024->1024) ----------------
__global__ void k_lin2(const float* __restrict__ gm, const float* __restrict__ btm,
                       const float* __restrict__ gs, const float* __restrict__ bts,
                       const float* __restrict__ w2m, const float* __restrict__ b2m,
                       const float* __restrict__ w2s, const float* __restrict__ b2s,
                       float* __restrict__ o_mu, float* __restrict__ o_sg) {
    int b = blockIdx.y, br = blockIdx.z;
    const float* g  = br ? gs  : gm;
    const float* bt = br ? bts : btm;
    const float* w2 = br ? w2s : w2m;
    const float* b2 = br ? b2s : b2m;
    __shared__ float hs[DV];
    __shared__ float red[8];
    __shared__ float mean_s, rstd_s;
    int tid = threadIdx.x, lane = tid & 31, wid = tid >> 5;
    const float* src = g_pre + (br * BB + b) * DV;
    for (int i = tid; i < DV; i += 256) hs[i] = src[i];
    __syncthreads();
    // mean
    float s = 0.f;
    for (int i = tid; i < DV; i += 256) s += hs[i];
    s = warp_sum(s);
    if (lane == 0) red[wid] = s;
    __syncthreads();
    if (tid == 0) {
        float m = 0.f;
        for (int i = 0; i < 8; i++) m += red[i];
        mean_s = m / (float)DV;
    }
    __syncthreads();
    float m = mean_s;
    // var
    float v = 0.f;
    for (int i = tid; i < DV; i += 256) { float d = hs[i] - m; v += d * d; }
    v = warp_sum(v);
    if (lane == 0) red[wid] = v;
    __syncthreads();
    if (tid == 0) {
        float vv = 0.f;
        for (int i = 0; i < 8; i++) vv += red[i];
        rstd_s = rsqrtf(vv / (float)DV + 1e-5f);
    }
    __syncthreads();
    float rstd = rstd_s;
    for (int i = tid; i < DV; i += 256)
        hs[i] = fmaxf((hs[i] - m) * rstd * g[i] + bt[i], 0.f);
    __syncthreads();

    int base = blockIdx.x * 64 + wid * 8;
#pragma unroll
    for (int oo = 0; oo < 8; oo++) {
        int o = base + oo;
        const float* wr = w2 + o * DV;
        float acc = 0.f;
#pragma unroll
        for (int i = lane; i < DV; i += 32) acc += wr[i] * hs[i];
        acc = warp_sum(acc);
        if (lane == 0) {
            float val = acc + b2[o];
            if (br == 0) {
                g_mu[b * DV + o] = val;
                o_mu[b * DV + o] = val;
            } else {
                float sp = fmaxf(val, 0.f) + log1pf(expf(-fabsf(val)));
                float sg = sp + 1e-6f;
                o_sg[b * DV + o] = sg;
                g_isg[b * DV + o] = 1.f / sg;
            }
        }
    }
}

// ---------------- kernel 3: Mahalanobis distance (256 MB stream), 2 rows/warp ----------------
__global__ void k_dist(const float* __restrict__ vf, float* __restrict__ o_dist) {
    __shared__ float4 mus[DV / 4];
    __shared__ float4 iss[DV / 4];
    int b = blockIdx.y;
    int tid = threadIdx.x, lane = tid & 31, wid = tid >> 5;
    if (tid < 256) mus[tid] = ((const float4*)(g_mu + b * DV))[tid];
    else           iss[tid - 256] = ((const float4*)(g_isg + b * DV))[tid - 256];
    __syncthreads();

    int t0 = (blockIdx.x * 16 + wid) * 2;
    const float4* v0 = (const float4*)(vf + ((size_t)b * TT + t0) * DV);
    const float4* v1 = v0 + DV / 4;
    float a0 = 0.f, a1 = 0.f;
#pragma unroll
    for (int it = 0; it < 8; it++) {
        int i = lane + it * 32;
        float4 x0 = v0[i], x1 = v1[i], mm = mus[i], ss = iss[i];
        float d;
        d = x0.x - mm.x; a0 += d * d * ss.x;
        d = x0.y - mm.y; a0 += d * d * ss.y;
        d = x0.z - mm.z; a0 += d * d * ss.z;
        d = x0.w - mm.w; a0 += d * d * ss.w;
        d = x1.x - mm.x; a1 += d * d * ss.x;
        d = x1.y - mm.y; a1 += d * d * ss.y;
        d = x1.z - mm.z; a1 += d * d * ss.z;
        d = x1.w - mm.w; a1 += d * d * ss.w;
    }
    a0 = warp_sum(a0);
    a1 = warp_sum(a1);
    if (lane == 0) {
        o_dist[b * TT + t0]     = a0;
        o_dist[b * TT + t0 + 1] = a1;
    }
}

// ---------------- kernel 4: median + top-18 (parallel radix) + diversify + gather ----------------
__device__ __forceinline__ unsigned long long sel_key(const float* __restrict__ drow,
                                                      int i, float med, int mode) {
    float x = drow[i];
    if (mode) {
        float d = fabsf(x - med);
        return ((unsigned long long)__float_as_uint(d) << 13) | (unsigned)i;
    }
    return (unsigned long long)__float_as_uint(x);
}

// one radix-select pass: narrows (prefix, k) by `bits` bits. 1024 threads.
__device__ void radix_pass(const float* __restrict__ drow, float med, int mode,
                           int shift, int bits,
                           unsigned* hist, unsigned* wsum, unsigned* wpfx,
                           unsigned long long* sh_prefix, int* sh_k) {
    int tid = threadIdx.x, lane = tid & 31, wid = tid >> 5;
    for (int j = tid; j < NB; j += 1024) hist[j] = 0u;
    __syncthreads();
    unsigned long long pfx = *sh_prefix;
    unsigned mask = (1u << bits) - 1u;
    for (int i = tid; i < TT; i += 1024) {
        unsigned long long key = sel_key(drow, i, med, mode);
        if ((key >> (shift + bits)) == pfx)
            atomicAdd(&hist[(unsigned)(key >> shift) & mask], 1u);
    }
    __syncthreads();
    // parallel locate: block-wide prefix over 4096 bins (4 bins/thread)
    unsigned s0 = hist[tid * 4], s1 = hist[tid * 4 + 1],
             s2 = hist[tid * 4 + 2], s3 = hist[tid * 4 + 3];
    unsigned s = s0 + s1 + s2 + s3;
    unsigned inc = s;
#pragma unroll
    for (int o = 1; o < 32; o <<= 1) {
        unsigned n = __shfl_up_sync(0xffffffffu, inc, o);
        if (lane >= o) inc += n;
    }
    if (lane == 31) wsum[wid] = inc;
    __syncthreads();
    if (wid == 0) {
        unsigned v = wsum[lane];
        unsigned iw = v;
#pragma unroll
        for (int o = 1; o < 32; o <<= 1) {
            unsigned n = __shfl_up_sync(0xffffffffu, iw, o);
            if (lane >= o) iw += n;
        }
        wpfx[lane] = iw - v;
    }
    __syncthreads();
    unsigned base = wpfx[wid] + (inc - s);
    unsigned k = (unsigned)*sh_k;
    if (k >= base && k < base + s) {   // exactly one thread
        unsigned off = base;
        int bin = tid * 4;
        if (k >= off + s0) { off += s0; bin++;
            if (k >= off + s1) { off += s1; bin++;
                if (k >= off + s2) { off += s2; bin++; } } }
        *sh_prefix = (pfx << bits) | (unsigned)bin;
        *sh_k = (int)(k - off);
    }
    __syncthreads();
}

__global__ void k_select(const float* __restrict__ dist, const float* __restrict__ vf,
                         float* __restrict__ o_idx, float* __restrict__ o_attn) {
    __shared__ unsigned hist[NB];
    __shared__ unsigned wsum[32], wpfx[32];
    __shared__ unsigned long long sh_prefix;
    __shared__ int sh_k;
    __shared__ unsigned long long ckeys[CC];
    __shared__ int sh_cnt;
    __shared__ int sels[KREP];

    int b = blockIdx.x;
    int tid = threadIdx.x;
    const float* drow = dist + b * TT;

    if (tid == 0) { sh_prefix = 0ull; sh_k = (TT - 1) / 2; }  // lower median rank
    __syncthreads();

    // median: 32-bit key (dist >= 0), passes 12+12+8
    radix_pass(drow, 0.f, 0, 20, 12, hist, wsum, wpfx, &sh_prefix, &sh_k);
    radix_pass(drow, 0.f, 0,  8, 12, hist, wsum, wpfx, &sh_prefix, &sh_k);
    radix_pass(drow, 0.f, 0,  0,  8, hist, wsum, wpfx, &sh_prefix, &sh_k);
    float med = __uint_as_float((unsigned)sh_prefix);
    __syncthreads();
    if (tid == 0) { sh_prefix = 0ull; sh_k = CC - 1; sh_cnt = 0; }
    __syncthreads();

    // top-18 smallest 45-bit key = bits(|d-med|)<<13 | idx, passes 12+12+12+9
    radix_pass(drow, med, 1, 33, 12, hist, wsum, wpfx, &sh_prefix, &sh_k);
    radix_pass(drow, med, 1, 21, 12, hist, wsum, wpfx, &sh_prefix, &sh_k);
    radix_pass(drow, med, 1,  9, 12, hist, wsum, wpfx, &sh_prefix, &sh_k);
    radix_pass(drow, med, 1,  0,  9, hist, wsum, wpfx, &sh_prefix, &sh_k);
    unsigned long long kt = sh_prefix;  // 18th-smallest key (keys unique)

    for (int i = tid; i < TT; i += 1024) {
        unsigned long long key = sel_key(drow, i, med, 1);
        if (key <= kt) {
            int p = atomicAdd(&sh_cnt, 1);
            if (p < CC) ckeys[p] = key;
        }
    }
    __syncthreads();

    if (tid == 0) {
        // sort ascending key == lax.top_k order (value asc, idx asc on ties)
        for (int i = 1; i < CC; i++) {
            unsigned long long kv = ckeys[i];
            int j = i - 1;
            while (j >= 0 && ckeys[j] > kv) { ckeys[j + 1] = ckeys[j]; j--; }
            ckeys[j + 1] = kv;
        }
        int cand[CC];
        for (int c = 0; c < CC; c++) cand[c] = (int)(ckeys[c] & 0x1FFFull);

        // greedy farthest-point diversify (first-occurrence argmax)
        const float NINF = __int_as_float(0xff800000);
        float candf[CC], mind[CC];
        int sel[KREP];
        for (int c = 0; c < CC; c++) candf[c] = (float)cand[c];
        for (int c = 0; c < CC; c++) mind[c] = fabsf(candf[c] - candf[0]);
        mind[0] = NINF;
        sel[0] = cand[0];
        for (int sI = 1; sI < KREP; sI++) {
            int best = 0;
            float bm = NINF;
            for (int c = 0; c < CC; c++)
                if (mind[c] > bm) { bm = mind[c]; best = c; }
            sel[sI] = cand[best];
            float cb = candf[best];
            for (int c = 0; c < CC; c++) mind[c] = fminf(mind[c], fabsf(candf[c] - cb));
            mind[best] = NINF;
        }
        for (int sI = 0; sI < KREP; sI++) {
            sels[sI] = sel[sI];
            o_idx[b * KREP + sI] = (float)sel[sI];
        }
    }
    __syncthreads();

    // zero attn-weight output for later atomicAdd accumulation
    if (tid < KREP * KREP) o_attn[b * KREP * KREP + tid] = 0.f;

    // gather rep
    for (int kk = 0; kk < KREP; kk++) {
        int t = sels[kk];
        const float* src = vf + ((size_t)b * TT + t) * DV;
        float* dst = g_rep + (b * KREP + kk) * DV;
        if (tid < DV) dst[tid] = src[tid];
    }
}

// ---------------- kernel 5: 48-row GEMM with smem-staged x ----------------
// mode 0: x=g_rep, out=g_qkv (stride 3*DV). mode 1: x=g_ao, out=out_ext (stride DV).
__global__ void k_gemm48(const float* __restrict__ w, const float* __restrict__ bias,
                         float* __restrict__ out_ext, int mode) {
    const float* x = mode ? g_ao : g_rep;
    float* out     = mode ? out_ext : g_qkv;
    int ostride    = mode ? DV : 3 * DV;

    __shared__ float4 xs[48 * 32];  // 48 rows x 128 floats = 24KB
    int tid = threadIdx.x, lane = tid & 31, wid = tid >> 5;
    int o = blockIdx.x * 8 + wid;
    const float4* wr = (const float4*)(w + o * DV);
    float acc[48];
#pragma unroll
    for (int r = 0; r < 48; r++) acc[r] = 0.f;

    for (int kc = 0; kc < 8; kc++) {
        __syncthreads();
        for (int i = tid; i < 48 * 32; i += 256)
            xs[i] = ((const float4*)(x + (i >> 5) * DV + kc * 128))[i & 31];
        __syncthreads();
        float4 wv = wr[kc * 32 + lane];
#pragma unroll
        for (int r = 0; r < 48; r++) {
            float4 xv = xs[r * 32 + lane];
            acc[r] += wv.x * xv.x + wv.y * xv.y + wv.z * xv.z + wv.w * xv.w;
        }
    }
#pragma unroll
    for (int off = 16; off; off >>= 1)
#pragma unroll
        for (int r = 0; r < 48; r++)
            acc[r] += __shfl_xor_sync(0xffffffffu, acc[r], off);
    float bs = bias[o];
#pragma unroll
    for (int r = 0; r < 48; r++)
        if (lane == (r & 31)) out[r * ostride + o] = acc[r] + bs;
}

// ---------------- kernel 6: 6-token attention per (b, h), fused head-mean ----------------
__global__ void k_attn(float* __restrict__ o_attn) {
    int b = blockIdx.x, h = blockIdx.y;
    __shared__ float qs[KREP * HD], ks[KREP * HD], vs[KREP * HD];
    int tid = threadIdx.x, lane = tid & 31, wid = tid >> 5;

    for (int i = tid; i < KREP * HD; i += 192) {
        int row = i / HD, d = i % HD;
        const float* base = g_qkv + (b * KREP + row) * 3 * DV + h * HD + d;
        qs[i] = base[0];
        ks[i] = base[DV];
        vs[i] = base[2 * DV];
    }
    __syncthreads();

    int i = wid;  // 6 warps, one query row each
    float sc[KREP];
    const float scale = 0.08838834764831845f;  // 1/sqrt(128)
    for (int j = 0; j < KREP; j++) {
        float acc = 0.f;
#pragma unroll
        for (int m = 0; m < 4; m++)
            acc += qs[i * HD + lane + 32 * m] * ks[j * HD + lane + 32 * m];
        acc = warp_sum(acc);
        sc[j] = acc * scale;
    }
    float mx = sc[0];
    for (int j = 1; j < KREP; j++) mx = fmaxf(mx, sc[j]);
    float den = 0.f;
    for (int j = 0; j < KREP; j++) { sc[j] = expf(sc[j] - mx); den += sc[j]; }
    float rden = 1.f / den;
    for (int j = 0; j < KREP; j++) sc[j] *= rden;
    if (lane < KREP)
        atomicAdd(&o_attn[(b * KREP + i) * KREP + lane], sc[lane] * (1.f / (float)NH));
    for (int d = lane; d < HD; d += 32) {
        float o = 0.f;
        for (int j = 0; j < KREP; j++) o += sc[j] * vs[j * HD + d];
        g_ao[(b * KREP + i) * DV + h * HD + d] = o;
    }
}

// ---------------- launcher ----------------
extern "C" void kernel_launch(void* const* d_in, const int* in_sizes, int n_in,
                              void* d_out, int out_size) {
    const float* vf    = (const float*)d_in[0];
    const float* qe    = (const float*)d_in[1];
    const float* mu_w1 = (const float*)d_in[2];
    const float* mu_b1 = (const float*)d_in[3];
    const float* mu_g  = (const float*)d_in[4];
    const float* mu_bt = (const float*)d_in[5];
    const float* mu_w2 = (const float*)d_in[6];
    const float* mu_b2 = (const float*)d_in[7];
    const float* sg_w1 = (const float*)d_in[8];
    const float* sg_b1 = (const float*)d_in[9];
    const float* sg_g  = (const float*)d_in[10];
    const float* sg_bt = (const float*)d_in[11];
    const float* sg_w2 = (const float*)d_in[12];
    const float* sg_b2 = (const float*)d_in[13];
    const float* in_w  = (const float*)d_in[14];
    const float* in_b  = (const float*)d_in[15];
    const float* out_w = (const float*)d_in[16];
    const float* out_b = (const float*)d_in[17];

    float* out = (float*)d_out;
    float* o_ref  = out;                    // [8,6,1024]  49152
    float* o_idx  = out + 49152;            // [8,6]       48
    float* o_dist = out + 49200;            // [8,8192]    65536
    float* o_mu   = out + 114736;           // [8,1024]    8192
    float* o_sg   = out + 122928;           // [8,1024]    8192
    float* o_attn = out + 131120;           // [8,6,6]     288

    k_lin1<<<dim3(DV / 64, BB, 2), 256>>>(qe, mu_w1, mu_b1, sg_w1, sg_b1);
    k_lin2<<<dim3(DV / 64, BB, 2), 256>>>(mu_g, mu_bt, sg_g, sg_bt,
                                          mu_w2, mu_b2, sg_w2, sg_b2, o_mu, o_sg);
    k_dist<<<dim3(TT / 32, BB), 512>>>(vf, o_dist);
    k_select<<<BB, 1024>>>(o_dist, vf, o_idx, o_attn);
    k_gemm48<<<3 * DV / 8, 256>>>(in_w, in_b, nullptr, 0);
    k_attn<<<dim3(BB, NH), 192>>>(o_attn);
    k_gemm48<<<DV / 8, 256>>>(out_w, out_b, o_ref, 1);
}

// round 6
// speedup vs baseline: 4.9851x; 1.1389x over previous
#include <cuda_runtime.h>
#include <math.h>

#define BB 8
#define TT 8192
#define DV 1024
#define DQ 768
#define KREP 6
#define NH 8
#define HD 128
#define CC 18     // K_REP*3 candidates
#define NB 2048   // radix histogram bins (11-bit)

// ---------------- scratch (no allocations allowed) ----------------
__device__ __align__(16) float g_pre[2 * BB * DV];       // pre-LN hidden
__device__ __align__(16) float g_mu[BB * DV];
__device__ __align__(16) float g_isg[BB * DV];           // 1/sigma
__device__ __align__(16) float g_rep[BB * KREP * DV];    // gathered features
__device__ __align__(16) float g_qkv[BB * KREP * 3 * DV];
__device__ __align__(16) float g_ao[BB * KREP * DV];     // attention output

__device__ __forceinline__ float warp_sum(float v) {
#pragma unroll
    for (int o = 16; o; o >>= 1) v += __shfl_xor_sync(0xffffffffu, v, o);
    return v;
}

// ---------------- kernel 0: zero attn output (also shifts profiler slot) ----------------
__global__ void k_zero(float* __restrict__ o_attn) {
    if (threadIdx.x < 288) o_attn[threadIdx.x] = 0.f;
}

// ---------------- kernel 1: Linear(768->1024), warp = 2 outputs ----------------
__global__ void k_lin1(const float* __restrict__ q,
                       const float* __restrict__ w1m, const float* __restrict__ b1m,
                       const float* __restrict__ w1s, const float* __restrict__ b1s) {
    int b = blockIdx.y, br = blockIdx.z;
    const float* w1 = br ? w1s : w1m;
    const float* b1 = br ? b1s : b1m;
    __shared__ float xs[DQ];
    int tid = threadIdx.x, lane = tid & 31, wid = tid >> 5;
    for (int i = tid; i < DQ; i += 256) xs[i] = q[b * DQ + i];
    __syncthreads();
    int base = blockIdx.x * 16 + wid * 2;
#pragma unroll
    for (int oo = 0; oo < 2; oo++) {
        int o = base + oo;
        const float* wr = w1 + o * DQ;
        float acc = 0.f;
#pragma unroll
        for (int i = lane; i < DQ; i += 32) acc += wr[i] * xs[i];
        acc = warp_sum(acc);
        if (lane == 0) g_pre[(br * BB + b) * DV + o] = acc + b1[o];
    }
}

// ---------------- kernel 2: LN+ReLU (recomputed per block) + Linear(1024->1024) ----------------
__global__ void k_lin2(const float* __restrict__ gm, const float* __restrict__ btm,
                       const float* __restrict__ gs, const float* __restrict__ bts,
                       const float* __restrict__ w2m, const float* __restrict__ b2m,
                       const float* __restrict__ w2s, const float* __restrict__ b2s,
                       float* __restrict__ o_mu, float* __restrict__ o_sg) {
    int b = blockIdx.y, br = blockIdx.z;
    const float* g  = br ? gs  : gm;
    const float* bt = br ? bts : btm;
    const float* w2 = br ? w2s : w2m;
    const float* b2 = br ? b2s : b2m;
    __shared__ float hs[DV];
    __shared__ float red[8];
    __shared__ float mean_s, rstd_s;
    int tid = threadIdx.x, lane = tid & 31, wid = tid >> 5;
    const float* src = g_pre + (br * BB + b) * DV;
    for (int i = tid; i < DV; i += 256) hs[i] = src[i];
    __syncthreads();
    float s = 0.f;
    for (int i = tid; i < DV; i += 256) s += hs[i];
    s = warp_sum(s);
    if (lane == 0) red[wid] = s;
    __syncthreads();
    if (tid == 0) {
        float m = 0.f;
        for (int i = 0; i < 8; i++) m += red[i];
        mean_s = m / (float)DV;
    }
    __syncthreads();
    float m = mean_s;
    float v = 0.f;
    for (int i = tid; i < DV; i += 256) { float d = hs[i] - m; v += d * d; }
    v = warp_sum(v);
    if (lane == 0) red[wid] = v;
    __syncthreads();
    if (tid == 0) {
        float vv = 0.f;
        for (int i = 0; i < 8; i++) vv += red[i];
        rstd_s = rsqrtf(vv / (float)DV + 1e-5f);
    }
    __syncthreads();
    float rstd = rstd_s;
    for (int i = tid; i < DV; i += 256)
        hs[i] = fmaxf((hs[i] - m) * rstd * g[i] + bt[i], 0.f);
    __syncthreads();

    int base = blockIdx.x * 16 + wid * 2;
#pragma unroll
    for (int oo = 0; oo < 2; oo++) {
        int o = base + oo;
        const float* wr = w2 + o * DV;
        float acc = 0.f;
#pragma unroll
        for (int i = lane; i < DV; i += 32) acc += wr[i] * hs[i];
        acc = warp_sum(acc);
        if (lane == 0) {
            float val = acc + b2[o];
            if (br == 0) {
                g_mu[b * DV + o] = val;
                o_mu[b * DV + o] = val;
            } else {
                float sp = fmaxf(val, 0.f) + log1pf(expf(-fabsf(val)));
                float sg = sp + 1e-6f;
                o_sg[b * DV + o] = sg;
                g_isg[b * DV + o] = 1.f / sg;
            }
        }
    }
}

// ---------------- kernel 3: Mahalanobis distance (256 MB stream), 2 rows/warp ----------------
__global__ void k_dist(const float* __restrict__ vf, float* __restrict__ o_dist) {
    __shared__ float4 mus[DV / 4];
    __shared__ float4 iss[DV / 4];
    int b = blockIdx.y;
    int tid = threadIdx.x, lane = tid & 31, wid = tid >> 5;
    if (tid < 256) mus[tid] = ((const float4*)(g_mu + b * DV))[tid];
    else           iss[tid - 256] = ((const float4*)(g_isg + b * DV))[tid - 256];
    __syncthreads();

    int t0 = (blockIdx.x * 16 + wid) * 2;
    const float4* v0 = (const float4*)(vf + ((size_t)b * TT + t0) * DV);
    const float4* v1 = v0 + DV / 4;
    float a0 = 0.f, a1 = 0.f;
#pragma unroll
    for (int it = 0; it < 8; it++) {
        int i = lane + it * 32;
        float4 x0 = v0[i], x1 = v1[i], mm = mus[i], ss = iss[i];
        float d;
        d = x0.x - mm.x; a0 += d * d * ss.x;
        d = x0.y - mm.y; a0 += d * d * ss.y;
        d = x0.z - mm.z; a0 += d * d * ss.z;
        d = x0.w - mm.w; a0 += d * d * ss.w;
        d = x1.x - mm.x; a1 += d * d * ss.x;
        d = x1.y - mm.y; a1 += d * d * ss.y;
        d = x1.z - mm.z; a1 += d * d * ss.z;
        d = x1.w - mm.w; a1 += d * d * ss.w;
    }
    a0 = warp_sum(a0);
    a1 = warp_sum(a1);
    if (lane == 0) {
        o_dist[b * TT + t0]     = a0;
        o_dist[b * TT + t0 + 1] = a1;
    }
}

// ---------------- kernel 4: median + top-18 (smem radix) + diversify + gather ----------------
// `first` pass accepts all keys (prefix empty) — avoids the 32-bit >>32 UB.
__device__ void radix_pass_s(const unsigned* __restrict__ keys,
                             int shift, int bits, bool first,
                             unsigned* hist, unsigned* wsum, unsigned* wpfx,
                             unsigned* sh_prefix, int* sh_k) {
    int tid = threadIdx.x, lane = tid & 31, wid = tid >> 5;
    hist[tid] = 0u;
    hist[tid + 1024] = 0u;
    __syncthreads();
    unsigned pfx = *sh_prefix;
    unsigned mask = (1u << bits) - 1u;
#pragma unroll
    for (int r = 0; r < 8; r++) {
        unsigned key = keys[tid + r * 1024];
        bool ok = first || ((key >> (shift + bits)) == pfx);
        if (ok) atomicAdd(&hist[(key >> shift) & mask], 1u);
    }
    __syncthreads();
    unsigned s0 = hist[tid * 2], s1 = hist[tid * 2 + 1];
    unsigned s = s0 + s1;
    unsigned inc = s;
#pragma unroll
    for (int o = 1; o < 32; o <<= 1) {
        unsigned n = __shfl_up_sync(0xffffffffu, inc, o);
        if (lane >= o) inc += n;
    }
    if (lane == 31) wsum[wid] = inc;
    __syncthreads();
    if (wid == 0) {
        unsigned v = wsum[lane];
        unsigned iw = v;
#pragma unroll
        for (int o = 1; o < 32; o <<= 1) {
            unsigned n = __shfl_up_sync(0xffffffffu, iw, o);
            if (lane >= o) iw += n;
        }
        wpfx[lane] = iw - v;
    }
    __syncthreads();
    unsigned base = wpfx[wid] + (inc - s);
    unsigned k = (unsigned)*sh_k;
    if (k >= base && k < base + s) {   // exactly one thread
        int bin = tid * 2;
        unsigned off = base;
        if (k >= off + s0) { off += s0; bin++; }
        *sh_prefix = (pfx << bits) | (unsigned)bin;
        *sh_k = (int)(k - off);
    }
    __syncthreads();
}

__global__ void k_select(const float* __restrict__ dist, const float* __restrict__ vf,
                         float* __restrict__ o_idx) {
    __shared__ unsigned keys[TT];          // 32 KB
    __shared__ unsigned hist[NB];          // 8 KB
    __shared__ unsigned wsum[32], wpfx[32];
    __shared__ unsigned sh_prefix;
    __shared__ int sh_k;
    __shared__ unsigned long long lessK[CC];
    __shared__ int eqIdx[64];
    __shared__ int sh_nless, sh_neq;
    __shared__ int sels[KREP];

    int b = blockIdx.x;
    int tid = threadIdx.x;
    const float* drow = dist + b * TT;

#pragma unroll
    for (int r = 0; r < 8; r++)
        keys[tid + r * 1024] = __float_as_uint(drow[tid + r * 1024]);
    if (tid == 0) { sh_prefix = 0u; sh_k = (TT - 1) / 2; }  // lower median rank
    __syncthreads();

    // median: 32-bit nonneg-float key, passes 11+11+10
    radix_pass_s(keys, 21, 11, true,  hist, wsum, wpfx, &sh_prefix, &sh_k);
    radix_pass_s(keys, 10, 11, false, hist, wsum, wpfx, &sh_prefix, &sh_k);
    radix_pass_s(keys,  0, 10, false, hist, wsum, wpfx, &sh_prefix, &sh_k);
    float med = __uint_as_float(sh_prefix);
    __syncthreads();

    // keys = bits(|dist - med|)
#pragma unroll
    for (int r = 0; r < 8; r++) {
        int i = tid + r * 1024;
        keys[i] = __float_as_uint(fabsf(__uint_as_float(keys[i]) - med));
    }
    if (tid == 0) { sh_prefix = 0u; sh_k = CC - 1; sh_nless = 0; sh_neq = 0; }
    __syncthreads();

    // rank-17 value (ties by multiplicity): passes 11+11+10
    radix_pass_s(keys, 21, 11, true,  hist, wsum, wpfx, &sh_prefix, &sh_k);
    radix_pass_s(keys, 10, 11, false, hist, wsum, wpfx, &sh_prefix, &sh_k);
    radix_pass_s(keys,  0, 10, false, hist, wsum, wpfx, &sh_prefix, &sh_k);
    unsigned vstar = sh_prefix;     // value of rank-17 element
    int n_eq_take = sh_k + 1;       // how many of the ==vstar group (smallest idx first)
    __syncthreads();

    // collect strictly-less (≤17 items) and equals (tie candidates)
#pragma unroll
    for (int r = 0; r < 8; r++) {
        int i = tid + r * 1024;
        unsigned key = keys[i];
        if (key < vstar) {
            int p = atomicAdd(&sh_nless, 1);
            lessK[p] = ((unsigned long long)key << 13) | (unsigned)i;
        } else if (key == vstar) {
            int p = atomicAdd(&sh_neq, 1);
            if (p < 64) eqIdx[p] = i;
        }
    }
    __syncthreads();

    if (tid == 0) {
        int nless = sh_nless;
        int neq = sh_neq < 64 ? sh_neq : 64;
        for (int i = 1; i < nless; i++) {           // sort by (value, idx) asc
            unsigned long long kv = lessK[i];
            int j = i - 1;
            while (j >= 0 && lessK[j] > kv) { lessK[j + 1] = lessK[j]; j--; }
            lessK[j + 1] = kv;
        }
        for (int i = 1; i < neq; i++) {             // sort idx asc
            int kv = eqIdx[i];
            int j = i - 1;
            while (j >= 0 && eqIdx[j] > kv) { eqIdx[j + 1] = eqIdx[j]; j--; }
            eqIdx[j + 1] = kv;
        }
        int cand[CC];
        for (int c = 0; c < nless; c++) cand[c] = (int)(lessK[c] & 0x1FFFull);
        for (int c = 0; c < n_eq_take && nless + c < CC; c++) cand[nless + c] = eqIdx[c];

        // greedy farthest-point diversify (first-occurrence argmax)
        const float NINF = __int_as_float(0xff800000);
        float candf[CC], mind[CC];
        int sel[KREP];
        for (int c = 0; c < CC; c++) candf[c] = (float)cand[c];
        for (int c = 0; c < CC; c++) mind[c] = fabsf(candf[c] - candf[0]);
        mind[0] = NINF;
        sel[0] = cand[0];
        for (int sI = 1; sI < KREP; sI++) {
            int best = 0;
            float bm = NINF;
            for (int c = 0; c < CC; c++)
                if (mind[c] > bm) { bm = mind[c]; best = c; }
            sel[sI] = cand[best];
            float cb = candf[best];
            for (int c = 0; c < CC; c++) mind[c] = fminf(mind[c], fabsf(candf[c] - cb));
            mind[best] = NINF;
        }
        for (int sI = 0; sI < KREP; sI++) {
            sels[sI] = sel[sI];
            o_idx[b * KREP + sI] = (float)sel[sI];
        }
    }
    __syncthreads();

    // gather rep
    for (int kk = 0; kk < KREP; kk++) {
        int t = sels[kk];
        const float* src = vf + ((size_t)b * TT + t) * DV;
        float* dst = g_rep + (b * KREP + kk) * DV;
        if (tid < DV) dst[tid] = src[tid];
    }
}

// ---------------- kernel 5: 48-row GEMM with smem-staged x ----------------
__global__ void k_gemm48(const float* __restrict__ w, const float* __restrict__ bias,
                         float* __restrict__ out_ext, int mode) {
    const float* x = mode ? g_ao : g_rep;
    float* out     = mode ? out_ext : g_qkv;
    int ostride    = mode ? DV : 3 * DV;

    __shared__ float4 xs[48 * 32];  // 24KB
    int tid = threadIdx.x, lane = tid & 31, wid = tid >> 5;
    int o = blockIdx.x * 8 + wid;
    const float4* wr = (const float4*)(w + o * DV);
    float acc[48];
#pragma unroll
    for (int r = 0; r < 48; r++) acc[r] = 0.f;

    for (int kc = 0; kc < 8; kc++) {
        __syncthreads();
        for (int i = tid; i < 48 * 32; i += 256)
            xs[i] = ((const float4*)(x + (i >> 5) * DV + kc * 128))[i & 31];
        __syncthreads();
        float4 wv = wr[kc * 32 + lane];
#pragma unroll
        for (int r = 0; r < 48; r++) {
            float4 xv = xs[r * 32 + lane];
            acc[r] += wv.x * xv.x + wv.y * xv.y + wv.z * xv.z + wv.w * xv.w;
        }
    }
#pragma unroll
    for (int off = 16; off; off >>= 1)
#pragma unroll
        for (int r = 0; r < 48; r++)
            acc[r] += __shfl_xor_sync(0xffffffffu, acc[r], off);
    float bs = bias[o];
#pragma unroll
    for (int r = 0; r < 48; r++)
        if (lane == (r & 31)) out[r * ostride + o] = acc[r] + bs;
}

// ---------------- kernel 6: 6-token attention per (b, h), fused head-mean ----------------
__global__ void k_attn(float* __restrict__ o_attn) {
    int b = blockIdx.x, h = blockIdx.y;
    __shared__ float qs[KREP * HD], ks[KREP * HD], vs[KREP * HD];
    int tid = threadIdx.x, lane = tid & 31, wid = tid >> 5;

    for (int i = tid; i < KREP * HD; i += 192) {
        int row = i / HD, d = i % HD;
        const float* base = g_qkv + (b * KREP + row) * 3 * DV + h * HD + d;
        qs[i] = base[0];
        ks[i] = base[DV];
        vs[i] = base[2 * DV];
    }
    __syncthreads();

    int i = wid;  // 6 warps, one query row each
    float sc[KREP];
    const float scale = 0.08838834764831845f;  // 1/sqrt(128)
    for (int j = 0; j < KREP; j++) {
        float acc = 0.f;
#pragma unroll
        for (int m = 0; m < 4; m++)
            acc += qs[i * HD + lane + 32 * m] * ks[j * HD + lane + 32 * m];
        acc = warp_sum(acc);
        sc[j] = acc * scale;
    }
    float mx = sc[0];
    for (int j = 1; j < KREP; j++) mx = fmaxf(mx, sc[j]);
    float den = 0.f;
    for (int j = 0; j < KREP; j++) { sc[j] = expf(sc[j] - mx); den += sc[j]; }
    float rden = 1.f / den;
    for (int j = 0; j < KREP; j++) sc[j] *= rden;
    if (lane < KREP)
        atomicAdd(&o_attn[(b * KREP + i) * KREP + lane], sc[lane] * (1.f / (float)NH));
    for (int d = lane; d < HD; d += 32) {
        float o = 0.f;
        for (int j = 0; j < KREP; j++) o += sc[j] * vs[j * HD + d];
        g_ao[(b * KREP + i) * DV + h * HD + d] = o;
    }
}

// ---------------- launcher ----------------
extern "C" void kernel_launch(void* const* d_in, const int* in_sizes, int n_in,
                              void* d_out, int out_size) {
    const float* vf    = (const float*)d_in[0];
    const float* qe    = (const float*)d_in[1];
    const float* mu_w1 = (const float*)d_in[2];
    const float* mu_b1 = (const float*)d_in[3];
    const float* mu_g  = (const float*)d_in[4];
    const float* mu_bt = (const float*)d_in[5];
    const float* mu_w2 = (const float*)d_in[6];
    const float* mu_b2 = (const float*)d_in[7];
    const float* sg_w1 = (const float*)d_in[8];
    const float* sg_b1 = (const float*)d_in[9];
    const float* sg_g  = (const float*)d_in[10];
    const float* sg_bt = (const float*)d_in[11];
    const float* sg_w2 = (const float*)d_in[12];
    const float* sg_b2 = (const float*)d_in[13];
    const float* in_w  = (const float*)d_in[14];
    const float* in_b  = (const float*)d_in[15];
    const float* out_w = (const float*)d_in[16];
    const float* out_b = (const float*)d_in[17];

    float* out = (float*)d_out;
    float* o_ref  = out;                    // [8,6,1024]  49152
    float* o_idx  = out + 49152;            // [8,6]       48
    float* o_dist = out + 49200;            // [8,8192]    65536
    float* o_mu   = out + 114736;           // [8,1024]    8192
    float* o_sg   = out + 122928;           // [8,1024]    8192
    float* o_attn = out + 131120;           // [8,6,6]     288

    k_zero<<<1, 288>>>(o_attn);
    k_lin1<<<dim3(DV / 16, BB, 2), 256>>>(qe, mu_w1, mu_b1, sg_w1, sg_b1);
    k_lin2<<<dim3(DV / 16, BB, 2), 256>>>(mu_g, mu_bt, sg_g, sg_bt,
                                          mu_w2, mu_b2, sg_w2, sg_b2, o_mu, o_sg);
    k_dist<<<dim3(TT / 32, BB), 512>>>(vf, o_dist);
    k_select<<<BB, 1024>>>(o_dist, vf, o_idx);
    k_gemm48<<<3 * DV / 8, 256>>>(in_w, in_b, nullptr, 0);
    k_attn<<<dim3(BB, NH), 192>>>(o_attn);
    k_gemm48<<<DV / 8, 256>>>(out_w, out_b, o_ref, 1);
}